// round 6
// baseline (speedup 1.0000x reference)
#include <cuda_runtime.h>

#define FULLMASK 0xffffffffu

// Problem dims (hardcoded)
#define Bb 4
#define Ss 2048
#define Dd 1024
#define Hh 16
#define HDIM 64
#define Mrows (Bb*Ss)   // 8192

// Scratch (static device globals: allocation-free per harness rules).
// __align__(16): these are accessed via float4 everywhere.
__device__ __align__(16) float g_q[Bb*Hh*Ss*HDIM];    // [B,H,S,hd]
__device__ __align__(16) float g_k[Bb*Hh*Ss*HDIM];
__device__ __align__(16) float g_v[Bb*Hh*Ss*HDIM];
__device__ __align__(16) float g_ctx[Mrows*Dd];       // [B*S, D]
__device__ __align__(16) float g_y[Mrows*Dd];         // residual+attn_out before LN

// ---------------------------------------------------------------------------
// Kernel 1: QKV projection  C[m,n] = x[m,:] . Wqkv[n,:] + b[n], scattered into
// q/k/v buffers laid out [B,H,S,hd].
// 64x64 block tile, 16x16 threads, 4x4 register tile, k-chunk 16.
// ---------------------------------------------------------------------------
__global__ __launch_bounds__(256) void qkv_gemm_kernel(
    const float* __restrict__ x, const float* __restrict__ w,
    const float* __restrict__ bias)
{
    __shared__ float As[16][64];   // [kk][m]
    __shared__ float Bs[16][64];   // [kk][n]
    const int m0 = blockIdx.y * 64;
    const int n0 = blockIdx.x * 64;
    const int tid = threadIdx.x;
    const int tx = tid & 15, ty = tid >> 4;
    const int lrow = tid >> 2;           // 0..63
    const int lc4  = (tid & 3) << 2;     // 0,4,8,12

    const float* ax = x + (size_t)(m0 + lrow) * Dd + lc4;
    const float* aw = w + (size_t)(n0 + lrow) * Dd + lc4;

    float acc[4][4];
    #pragma unroll
    for (int i = 0; i < 4; i++)
        #pragma unroll
        for (int j = 0; j < 4; j++) acc[i][j] = 0.f;

    for (int kt = 0; kt < Dd/16; kt++) {
        float4 va = *(const float4*)(ax + kt*16);
        float4 vb = *(const float4*)(aw + kt*16);
        __syncthreads();
        As[lc4+0][lrow]=va.x; As[lc4+1][lrow]=va.y; As[lc4+2][lrow]=va.z; As[lc4+3][lrow]=va.w;
        Bs[lc4+0][lrow]=vb.x; Bs[lc4+1][lrow]=vb.y; Bs[lc4+2][lrow]=vb.z; Bs[lc4+3][lrow]=vb.w;
        __syncthreads();
        #pragma unroll
        for (int kk = 0; kk < 16; kk++) {
            float4 a4 = *(const float4*)&As[kk][ty<<2];
            float4 b4 = *(const float4*)&Bs[kk][tx<<2];
            float a[4] = {a4.x,a4.y,a4.z,a4.w};
            float b[4] = {b4.x,b4.y,b4.z,b4.w};
            #pragma unroll
            for (int i = 0; i < 4; i++)
                #pragma unroll
                for (int j = 0; j < 4; j++)
                    acc[i][j] = fmaf(a[i], b[j], acc[i][j]);
        }
    }

    // Epilogue: scatter into q/k/v [B,H,S,hd]
    const int n_base = n0 + (tx<<2);
    const int which  = n_base >> 10;       // 0=q,1=k,2=v (constant per block)
    const int dcol   = n_base & 1023;
    const int h      = dcol >> 6;
    const int e0     = dcol & 63;
    float* dst = (which == 0) ? g_q : (which == 1) ? g_k : g_v;
    float4 bb = *(const float4*)&bias[n_base];
    #pragma unroll
    for (int i = 0; i < 4; i++) {
        int m = m0 + (ty<<2) + i;
        int bidx = m >> 11;                // /2048
        int srow = m & 2047;
        float4 v;
        v.x = acc[i][0]+bb.x; v.y = acc[i][1]+bb.y;
        v.z = acc[i][2]+bb.z; v.w = acc[i][3]+bb.w;
        *(float4*)&dst[(((size_t)(bidx*Hh + h))*Ss + srow)*HDIM + e0] = v;
    }
}

// ---------------------------------------------------------------------------
// Kernel 2: causal flash attention, fp32. One block per (q-tile 64, bh).
// Online softmax; K-tile shared buffer is reused for P (XOR-swizzled, c&28).
// Static smem = 3 * 16KB = 48KB exactly.
// ---------------------------------------------------------------------------
__global__ __launch_bounds__(256) void attn_kernel()
{
    __shared__ float Qs[64][64];   // [d][r]
    __shared__ float KP[64*64];    // phase 1: K[c][d^swz(c)]; phase 2: P[c][r^swz(c)]
    __shared__ float Vs[64][64];   // [c][d]

    const int qt = blockIdx.x, bh = blockIdx.y;
    const int q0 = qt * 64;
    const size_t base = (size_t)bh * Ss * HDIM;
    const float* qg = g_q + base;
    const float* kg = g_k + base;
    const float* vg = g_v + base;
    const int tid = threadIdx.x;
    const int tx = tid & 15, ty = tid >> 4;

    // Load Q tile transposed to [d][r], pre-scaled by 1/sqrt(hd)=0.125
    #pragma unroll
    for (int it = 0; it < 4; it++) {
        int f = tid + it*256;
        int r = f >> 4, c4 = (f & 15) << 2;
        float4 v4 = *(const float4*)&qg[(size_t)(q0 + r)*HDIM + c4];
        Qs[c4+0][r] = v4.x*0.125f; Qs[c4+1][r] = v4.y*0.125f;
        Qs[c4+2][r] = v4.z*0.125f; Qs[c4+3][r] = v4.w*0.125f;
    }

    float m_i[4], l_i[4], o[4][4];
    #pragma unroll
    for (int i = 0; i < 4; i++) {
        m_i[i] = -3e38f; l_i[i] = 0.f;
        #pragma unroll
        for (int j = 0; j < 4; j++) o[i][j] = 0.f;
    }

    for (int kt = 0; kt <= qt; kt++) {
        const int k0 = kt * 64;
        __syncthreads();   // prev iter done reading KP(P)/Vs; also orders Qs writes
        #pragma unroll
        for (int it = 0; it < 4; it++) {
            int f = tid + it*256;
            int r = f >> 4, c4 = (f & 15) << 2;
            float4 kv = *(const float4*)&kg[(size_t)(k0 + r)*HDIM + c4];
            *(float4*)&KP[(r<<6) | (c4 ^ (r & 28))] = kv;
            float4 vv = *(const float4*)&vg[(size_t)(k0 + r)*HDIM + c4];
            *(float4*)&Vs[r][c4] = vv;
        }
        __syncthreads();

        // S = Q . K^T (scaled): 4x4 per thread, outer product over d
        float s[4][4];
        #pragma unroll
        for (int i = 0; i < 4; i++)
            #pragma unroll
            for (int j = 0; j < 4; j++) s[i][j] = 0.f;

        #pragma unroll 8
        for (int d = 0; d < 64; d++) {
            float4 a4 = *(const float4*)&Qs[d][ty<<2];
            float a[4] = {a4.x,a4.y,a4.z,a4.w};
            #pragma unroll
            for (int j = 0; j < 4; j++) {
                int c = (tx<<2) + j;
                float bv = KP[(c<<6) | (d ^ (c & 28))];
                s[0][j] = fmaf(a[0], bv, s[0][j]);
                s[1][j] = fmaf(a[1], bv, s[1][j]);
                s[2][j] = fmaf(a[2], bv, s[2][j]);
                s[3][j] = fmaf(a[3], bv, s[3][j]);
            }
        }

        if (kt == qt) {  // diagonal tile: mask keys above query
            #pragma unroll
            for (int i = 0; i < 4; i++)
                #pragma unroll
                for (int j = 0; j < 4; j++)
                    if (((tx<<2)+j) > ((ty<<2)+i)) s[i][j] = -3e38f;
        }

        // Online softmax per row (row group = 16 lanes sharing ty)
        #pragma unroll
        for (int i = 0; i < 4; i++) {
            float mt = fmaxf(fmaxf(s[i][0], s[i][1]), fmaxf(s[i][2], s[i][3]));
            #pragma unroll
            for (int ofs = 8; ofs > 0; ofs >>= 1)
                mt = fmaxf(mt, __shfl_xor_sync(FULLMASK, mt, ofs));
            float nm = fmaxf(m_i[i], mt);
            float alpha = __expf(m_i[i] - nm);
            float rs = 0.f;
            #pragma unroll
            for (int j = 0; j < 4; j++) {
                float p = __expf(s[i][j] - nm);
                s[i][j] = p; rs += p;
            }
            #pragma unroll
            for (int ofs = 8; ofs > 0; ofs >>= 1)
                rs += __shfl_xor_sync(FULLMASK, rs, ofs);
            l_i[i] = l_i[i]*alpha + rs;
            m_i[i] = nm;
            #pragma unroll
            for (int j = 0; j < 4; j++) o[i][j] *= alpha;
        }

        __syncthreads();  // all threads done reading K region
        #pragma unroll
        for (int i = 0; i < 4; i++)
            #pragma unroll
            for (int j = 0; j < 4; j++) {
                int c = (tx<<2) + j, r = (ty<<2) + i;
                KP[(c<<6) | (r ^ (c & 28))] = s[i][j];
            }
        __syncthreads();

        // O += P . V : outer product over c
        #pragma unroll 8
        for (int c = 0; c < 64; c++) {
            float4 v4 = *(const float4*)&Vs[c][tx<<2];
            float vv[4] = {v4.x,v4.y,v4.z,v4.w};
            #pragma unroll
            for (int i = 0; i < 4; i++) {
                float p = KP[(c<<6) | (((ty<<2)+i) ^ (c & 28))];
                o[i][0] = fmaf(p, vv[0], o[i][0]);
                o[i][1] = fmaf(p, vv[1], o[i][1]);
                o[i][2] = fmaf(p, vv[2], o[i][2]);
                o[i][3] = fmaf(p, vv[3], o[i][3]);
            }
        }
    }

    // Write ctx in [B,S,D] layout (D col = h*64 + e)
    const int b = bh >> 4, h = bh & 15;
    #pragma unroll
    for (int i = 0; i < 4; i++) {
        float inv = 1.f / l_i[i];
        int qrow = q0 + (ty<<2) + i;
        float4 v;
        v.x = o[i][0]*inv; v.y = o[i][1]*inv;
        v.z = o[i][2]*inv; v.w = o[i][3]*inv;
        *(float4*)&g_ctx[((size_t)(b*Ss + qrow))*Dd + h*HDIM + (tx<<2)] = v;
    }
}

// ---------------------------------------------------------------------------
// Kernel 3: out projection + bias + residual: y = ctx . Wout^T + b + x
// ---------------------------------------------------------------------------
__global__ __launch_bounds__(256) void out_gemm_kernel(
    const float* __restrict__ x, const float* __restrict__ w,
    const float* __restrict__ bias)
{
    __shared__ float As[16][64];
    __shared__ float Bs[16][64];
    const int m0 = blockIdx.y * 64;
    const int n0 = blockIdx.x * 64;
    const int tid = threadIdx.x;
    const int tx = tid & 15, ty = tid >> 4;
    const int lrow = tid >> 2;
    const int lc4  = (tid & 3) << 2;

    const float* ax = g_ctx + (size_t)(m0 + lrow) * Dd + lc4;
    const float* aw = w + (size_t)(n0 + lrow) * Dd + lc4;

    float acc[4][4];
    #pragma unroll
    for (int i = 0; i < 4; i++)
        #pragma unroll
        for (int j = 0; j < 4; j++) acc[i][j] = 0.f;

    for (int kt = 0; kt < Dd/16; kt++) {
        float4 va = *(const float4*)(ax + kt*16);
        float4 vb = *(const float4*)(aw + kt*16);
        __syncthreads();
        As[lc4+0][lrow]=va.x; As[lc4+1][lrow]=va.y; As[lc4+2][lrow]=va.z; As[lc4+3][lrow]=va.w;
        Bs[lc4+0][lrow]=vb.x; Bs[lc4+1][lrow]=vb.y; Bs[lc4+2][lrow]=vb.z; Bs[lc4+3][lrow]=vb.w;
        __syncthreads();
        #pragma unroll
        for (int kk = 0; kk < 16; kk++) {
            float4 a4 = *(const float4*)&As[kk][ty<<2];
            float4 b4 = *(const float4*)&Bs[kk][tx<<2];
            float a[4] = {a4.x,a4.y,a4.z,a4.w};
            float b[4] = {b4.x,b4.y,b4.z,b4.w};
            #pragma unroll
            for (int i = 0; i < 4; i++)
                #pragma unroll
                for (int j = 0; j < 4; j++)
                    acc[i][j] = fmaf(a[i], b[j], acc[i][j]);
        }
    }

    const int n_base = n0 + (tx<<2);
    float4 bb = *(const float4*)&bias[n_base];
    #pragma unroll
    for (int i = 0; i < 4; i++) {
        int m = m0 + (ty<<2) + i;
        float4 rx = *(const float4*)&x[(size_t)m*Dd + n_base];
        float4 v;
        v.x = acc[i][0]+bb.x+rx.x; v.y = acc[i][1]+bb.y+rx.y;
        v.z = acc[i][2]+bb.z+rx.z; v.w = acc[i][3]+bb.w+rx.w;
        *(float4*)&g_y[(size_t)m*Dd + n_base] = v;
    }
}

// ---------------------------------------------------------------------------
// Kernel 4: LayerNorm over D=1024. One block (256 threads) per row.
// ---------------------------------------------------------------------------
__global__ __launch_bounds__(256) void ln_kernel(
    const float* __restrict__ gamma, const float* __restrict__ beta,
    float* __restrict__ out)
{
    const int row = blockIdx.x;
    const int tid = threadIdx.x;
    const float* y = g_y + (size_t)row * Dd;
    float4 v = *(const float4*)&y[tid<<2];
    float s  = v.x + v.y + v.z + v.w;
    float s2 = v.x*v.x + v.y*v.y + v.z*v.z + v.w*v.w;
    #pragma unroll
    for (int ofs = 16; ofs > 0; ofs >>= 1) {
        s  += __shfl_xor_sync(FULLMASK, s,  ofs);
        s2 += __shfl_xor_sync(FULLMASK, s2, ofs);
    }
    __shared__ float ps[8], ps2[8];
    if ((tid & 31) == 0) { ps[tid>>5] = s; ps2[tid>>5] = s2; }
    __syncthreads();
    float tot = 0.f, tot2 = 0.f;
    #pragma unroll
    for (int wdx = 0; wdx < 8; wdx++) { tot += ps[wdx]; tot2 += ps2[wdx]; }
    float mu  = tot * (1.f/1024.f);
    float var = tot2 * (1.f/1024.f) - mu*mu;
    float rstd = rsqrtf(var + 1e-5f);
    float4 g4 = *(const float4*)&gamma[tid<<2];
    float4 b4 = *(const float4*)&beta[tid<<2];
    float4 r;
    r.x = (v.x-mu)*rstd*g4.x + b4.x;
    r.y = (v.y-mu)*rstd*g4.y + b4.y;
    r.z = (v.z-mu)*rstd*g4.z + b4.z;
    r.w = (v.w-mu)*rstd*g4.w + b4.w;
    *(float4*)&out[(size_t)row*Dd + (tid<<2)] = r;
}

// ---------------------------------------------------------------------------
extern "C" void kernel_launch(void* const* d_in, const int* in_sizes, int n_in,
                              void* d_out, int out_size)
{
    const float* x     = (const float*)d_in[0];
    const float* w_in  = (const float*)d_in[1];
    const float* b_in  = (const float*)d_in[2];
    const float* w_out = (const float*)d_in[3];
    const float* b_out = (const float*)d_in[4];
    const float* gamma = (const float*)d_in[5];
    const float* beta  = (const float*)d_in[6];
    float* out = (float*)d_out;

    qkv_gemm_kernel<<<dim3(48, 128), 256>>>(x, w_in, b_in);   // N=3072 tiles, M=8192 tiles
    attn_kernel   <<<dim3(32, 64),  256>>>();                 // 32 q-tiles x 64 bh
    out_gemm_kernel<<<dim3(16, 128), 256>>>(x, w_out, b_out); // N=1024 tiles
    ln_kernel     <<<8192, 256>>>(gamma, beta, out);
}

// round 17
// speedup vs baseline: 1.6206x; 1.6206x over previous
#include <cuda_runtime.h>
#include <cuda_bf16.h>
#include <cstdint>

#define FULLMASK 0xffffffffu

// Problem dims (hardcoded)
#define Bb 4
#define Ss 2048
#define Dd 1024
#define Hh 16
#define HDIM 64
#define Mrows (Bb*Ss)   // 8192

// Scratch (static device globals: allocation-free per harness rules).
__device__ __align__(16) float g_q[Bb*Hh*Ss*HDIM];    // [B,H,S,hd]
__device__ __align__(16) float g_k[Bb*Hh*Ss*HDIM];
__device__ __align__(16) float g_v[Bb*Hh*Ss*HDIM];
__device__ __align__(16) float g_ctx[Mrows*Dd];       // [B*S, D]
__device__ __align__(16) float g_y[Mrows*Dd];         // residual+attn_out before LN

// bf16 mma m16n8k16, fp32 accumulate
#define MMA_BF16(C, A, B) \
    asm volatile("mma.sync.aligned.m16n8k16.row.col.f32.bf16.bf16.f32 " \
        "{%0,%1,%2,%3},{%4,%5,%6,%7},{%8,%9},{%0,%1,%2,%3};" \
        : "+f"((C)[0]), "+f"((C)[1]), "+f"((C)[2]), "+f"((C)[3]) \
        : "r"((A)[0]), "r"((A)[1]), "r"((A)[2]), "r"((A)[3]), \
          "r"((B)[0]), "r"((B)[1]))

// ---------------------------------------------------------------------------
// Tensor-core GEMM (bf16 3-term split): C[m,n] = A[m,:] . B[n,:]  (A,B fp32
// row-major with K contiguous). Block tile 128x128x32, 8 warps (4m x 2n),
// warp tile 32x64. Smem padded to 40 bf16/row: 80B stride = 20 banks ->
// conflict-free fragment loads.
// ---------------------------------------------------------------------------
#define GEMM_MAINLOOP(APTR, BPTR)                                              \
    __shared__ __align__(16) __nv_bfloat16 Ah[128][40], Al[128][40];           \
    __shared__ __align__(16) __nv_bfloat16 Bh[128][40], Bl[128][40];           \
    const int m0 = blockIdx.y * 128;                                           \
    const int n0 = blockIdx.x * 128;                                           \
    const int tid  = threadIdx.x;                                              \
    const int warp = tid >> 5, lane = tid & 31;                                \
    const int wm = warp >> 1, wn = warp & 1;   /* 4 x 2 warp grid */           \
    const int m_base = wm * 32, n_base = wn * 64;                              \
    const int grp = lane >> 2, qid = lane & 3;                                 \
    const int lrow = tid >> 3;                 /* 0..31 */                     \
    const int lc   = (tid & 7) << 2;           /* 0,4,...,28 */                \
    float c[2][8][4];                                                          \
    _Pragma("unroll")                                                          \
    for (int mt = 0; mt < 2; mt++)                                             \
        _Pragma("unroll")                                                      \
        for (int nt = 0; nt < 8; nt++)                                         \
            _Pragma("unroll")                                                  \
            for (int r = 0; r < 4; r++) c[mt][nt][r] = 0.f;                    \
    for (int kt = 0; kt < Dd/32; kt++) {                                       \
        __syncthreads();                                                       \
        _Pragma("unroll")                                                      \
        for (int p = 0; p < 4; p++) {                                          \
            int r = lrow + p*32;                                               \
            float4 va = *(const float4*)&(APTR)[(size_t)(m0 + r)*Dd + kt*32 + lc]; \
            float4 vb = *(const float4*)&(BPTR)[(size_t)(n0 + r)*Dd + kt*32 + lc]; \
            __nv_bfloat16 h0 = __float2bfloat16(va.x);                         \
            __nv_bfloat16 h1 = __float2bfloat16(va.y);                         \
            __nv_bfloat16 h2 = __float2bfloat16(va.z);                         \
            __nv_bfloat16 h3 = __float2bfloat16(va.w);                         \
            *(__nv_bfloat162*)&Ah[r][lc+0] = __halves2bfloat162(h0, h1);       \
            *(__nv_bfloat162*)&Ah[r][lc+2] = __halves2bfloat162(h2, h3);       \
            *(__nv_bfloat162*)&Al[r][lc+0] = __halves2bfloat162(                \
                __float2bfloat16(va.x - __bfloat162float(h0)),                 \
                __float2bfloat16(va.y - __bfloat162float(h1)));                \
            *(__nv_bfloat162*)&Al[r][lc+2] = __halves2bfloat162(                \
                __float2bfloat16(va.z - __bfloat162float(h2)),                 \
                __float2bfloat16(va.w - __bfloat162float(h3)));                \
            __nv_bfloat16 g0 = __float2bfloat16(vb.x);                         \
            __nv_bfloat16 g1 = __float2bfloat16(vb.y);                         \
            __nv_bfloat16 g2 = __float2bfloat16(vb.z);                         \
            __nv_bfloat16 g3 = __float2bfloat16(vb.w);                         \
            *(__nv_bfloat162*)&Bh[r][lc+0] = __halves2bfloat162(g0, g1);       \
            *(__nv_bfloat162*)&Bh[r][lc+2] = __halves2bfloat162(g2, g3);       \
            *(__nv_bfloat162*)&Bl[r][lc+0] = __halves2bfloat162(                \
                __float2bfloat16(vb.x - __bfloat162float(g0)),                 \
                __float2bfloat16(vb.y - __bfloat162float(g1)));                \
            *(__nv_bfloat162*)&Bl[r][lc+2] = __halves2bfloat162(                \
                __float2bfloat16(vb.z - __bfloat162float(g2)),                 \
                __float2bfloat16(vb.w - __bfloat162float(g3)));                \
        }                                                                      \
        __syncthreads();                                                       \
        _Pragma("unroll")                                                      \
        for (int s = 0; s < 32; s += 16) {                                     \
            uint32_t ah[2][4], al[2][4], bhf[8][2], blf[8][2];                 \
            _Pragma("unroll")                                                  \
            for (int mt = 0; mt < 2; mt++) {                                   \
                int row = m_base + mt*16 + grp;                                \
                ah[mt][0] = *(const uint32_t*)&Ah[row  ][s + 2*qid];           \
                ah[mt][1] = *(const uint32_t*)&Ah[row+8][s + 2*qid];           \
                ah[mt][2] = *(const uint32_t*)&Ah[row  ][s + 2*qid + 8];       \
                ah[mt][3] = *(const uint32_t*)&Ah[row+8][s + 2*qid + 8];       \
                al[mt][0] = *(const uint32_t*)&Al[row  ][s + 2*qid];           \
                al[mt][1] = *(const uint32_t*)&Al[row+8][s + 2*qid];           \
                al[mt][2] = *(const uint32_t*)&Al[row  ][s + 2*qid + 8];       \
                al[mt][3] = *(const uint32_t*)&Al[row+8][s + 2*qid + 8];       \
            }                                                                  \
            _Pragma("unroll")                                                  \
            for (int nt = 0; nt < 8; nt++) {                                   \
                int col = n_base + nt*8 + grp;                                 \
                bhf[nt][0] = *(const uint32_t*)&Bh[col][s + 2*qid];            \
                bhf[nt][1] = *(const uint32_t*)&Bh[col][s + 2*qid + 8];        \
                blf[nt][0] = *(const uint32_t*)&Bl[col][s + 2*qid];            \
                blf[nt][1] = *(const uint32_t*)&Bl[col][s + 2*qid + 8];        \
            }                                                                  \
            _Pragma("unroll")                                                  \
            for (int mt = 0; mt < 2; mt++)                                     \
                _Pragma("unroll")                                              \
                for (int nt = 0; nt < 8; nt++) {                               \
                    MMA_BF16(c[mt][nt], ah[mt], bhf[nt]);                      \
                    MMA_BF16(c[mt][nt], ah[mt], blf[nt]);                      \
                    MMA_BF16(c[mt][nt], al[mt], bhf[nt]);                      \
                }                                                              \
        }                                                                      \
    }

// ---------------------------------------------------------------------------
// Kernel 1: QKV projection, scattered into q/k/v [B,H,S,hd].
// ---------------------------------------------------------------------------
__global__ __launch_bounds__(256) void qkv_gemm_kernel(
    const float* __restrict__ x, const float* __restrict__ w,
    const float* __restrict__ bias)
{
    GEMM_MAINLOOP(x, w)

    // Epilogue: n0 block lies entirely inside q, k, or v (boundaries 1024/2048
    // are multiples of 128).
    const int which = n0 >> 10;
    float* dst = (which == 0) ? g_q : (which == 1) ? g_k : g_v;
    #pragma unroll
    for (int mt = 0; mt < 2; mt++) {
        #pragma unroll
        for (int nt = 0; nt < 8; nt++) {
            int col  = n0 + n_base + nt*8 + 2*qid;
            int dcol = col & 1023;
            int h    = dcol >> 6;
            int e0   = dcol & 63;
            float bx = bias[col], by = bias[col+1];
            #pragma unroll
            for (int half = 0; half < 2; half++) {
                int m = m0 + m_base + mt*16 + grp + half*8;
                int bidx = m >> 11, srow = m & 2047;
                float2 v;
                v.x = c[mt][nt][half*2+0] + bx;
                v.y = c[mt][nt][half*2+1] + by;
                *(float2*)&dst[(((size_t)(bidx*Hh + h))*Ss + srow)*HDIM + e0] = v;
            }
        }
    }
}

// ---------------------------------------------------------------------------
// Kernel 3: out projection + bias + residual: y = ctx . Wout^T + b + x
// ---------------------------------------------------------------------------
__global__ __launch_bounds__(256) void out_gemm_kernel(
    const float* __restrict__ x, const float* __restrict__ w,
    const float* __restrict__ bias)
{
    GEMM_MAINLOOP(g_ctx, w)

    #pragma unroll
    for (int mt = 0; mt < 2; mt++) {
        #pragma unroll
        for (int nt = 0; nt < 8; nt++) {
            int col = n0 + n_base + nt*8 + 2*qid;
            float bx = bias[col], by = bias[col+1];
            #pragma unroll
            for (int half = 0; half < 2; half++) {
                int m = m0 + m_base + mt*16 + grp + half*8;
                float2 rx = *(const float2*)&x[(size_t)m*Dd + col];
                float2 v;
                v.x = c[mt][nt][half*2+0] + bx + rx.x;
                v.y = c[mt][nt][half*2+1] + by + rx.y;
                *(float2*)&g_y[(size_t)m*Dd + col] = v;
            }
        }
    }
}

// ---------------------------------------------------------------------------
// Kernel 2: causal flash attention, fp32 (unchanged this round).
// ---------------------------------------------------------------------------
__global__ __launch_bounds__(256) void attn_kernel()
{
    __shared__ float Qs[64][64];   // [d][r]
    __shared__ float KP[64*64];    // phase 1: K[c][d^swz(c)]; phase 2: P[c][r^swz(c)]
    __shared__ float Vs[64][64];   // [c][d]

    const int qt = blockIdx.x, bh = blockIdx.y;
    const int q0 = qt * 64;
    const size_t base = (size_t)bh * Ss * HDIM;
    const float* qg = g_q + base;
    const float* kg = g_k + base;
    const float* vg = g_v + base;
    const int tid = threadIdx.x;
    const int tx = tid & 15, ty = tid >> 4;

    #pragma unroll
    for (int it = 0; it < 4; it++) {
        int f = tid + it*256;
        int r = f >> 4, c4 = (f & 15) << 2;
        float4 v4 = *(const float4*)&qg[(size_t)(q0 + r)*HDIM + c4];
        Qs[c4+0][r] = v4.x*0.125f; Qs[c4+1][r] = v4.y*0.125f;
        Qs[c4+2][r] = v4.z*0.125f; Qs[c4+3][r] = v4.w*0.125f;
    }

    float m_i[4], l_i[4], o[4][4];
    #pragma unroll
    for (int i = 0; i < 4; i++) {
        m_i[i] = -3e38f; l_i[i] = 0.f;
        #pragma unroll
        for (int j = 0; j < 4; j++) o[i][j] = 0.f;
    }

    for (int kt = 0; kt <= qt; kt++) {
        const int k0 = kt * 64;
        __syncthreads();
        #pragma unroll
        for (int it = 0; it < 4; it++) {
            int f = tid + it*256;
            int r = f >> 4, c4 = (f & 15) << 2;
            float4 kv = *(const float4*)&kg[(size_t)(k0 + r)*HDIM + c4];
            *(float4*)&KP[(r<<6) | (c4 ^ (r & 28))] = kv;
            float4 vv = *(const float4*)&vg[(size_t)(k0 + r)*HDIM + c4];
            *(float4*)&Vs[r][c4] = vv;
        }
        __syncthreads();

        float s[4][4];
        #pragma unroll
        for (int i = 0; i < 4; i++)
            #pragma unroll
            for (int j = 0; j < 4; j++) s[i][j] = 0.f;

        #pragma unroll 8
        for (int d = 0; d < 64; d++) {
            float4 a4 = *(const float4*)&Qs[d][ty<<2];
            float a[4] = {a4.x,a4.y,a4.z,a4.w};
            #pragma unroll
            for (int j = 0; j < 4; j++) {
                int cc = (tx<<2) + j;
                float bv = KP[(cc<<6) | (d ^ (cc & 28))];
                s[0][j] = fmaf(a[0], bv, s[0][j]);
                s[1][j] = fmaf(a[1], bv, s[1][j]);
                s[2][j] = fmaf(a[2], bv, s[2][j]);
                s[3][j] = fmaf(a[3], bv, s[3][j]);
            }
        }

        if (kt == qt) {
            #pragma unroll
            for (int i = 0; i < 4; i++)
                #pragma unroll
                for (int j = 0; j < 4; j++)
                    if (((tx<<2)+j) > ((ty<<2)+i)) s[i][j] = -3e38f;
        }

        #pragma unroll
        for (int i = 0; i < 4; i++) {
            float mt = fmaxf(fmaxf(s[i][0], s[i][1]), fmaxf(s[i][2], s[i][3]));
            #pragma unroll
            for (int ofs = 8; ofs > 0; ofs >>= 1)
                mt = fmaxf(mt, __shfl_xor_sync(FULLMASK, mt, ofs));
            float nm = fmaxf(m_i[i], mt);
            float alpha = __expf(m_i[i] - nm);
            float rs = 0.f;
            #pragma unroll
            for (int j = 0; j < 4; j++) {
                float p = __expf(s[i][j] - nm);
                s[i][j] = p; rs += p;
            }
            #pragma unroll
            for (int ofs = 8; ofs > 0; ofs >>= 1)
                rs += __shfl_xor_sync(FULLMASK, rs, ofs);
            l_i[i] = l_i[i]*alpha + rs;
            m_i[i] = nm;
            #pragma unroll
            for (int j = 0; j < 4; j++) o[i][j] *= alpha;
        }

        __syncthreads();
        #pragma unroll
        for (int i = 0; i < 4; i++)
            #pragma unroll
            for (int j = 0; j < 4; j++) {
                int cc = (tx<<2) + j, r = (ty<<2) + i;
                KP[(cc<<6) | (r ^ (cc & 28))] = s[i][j];
            }
        __syncthreads();

        #pragma unroll 8
        for (int cc = 0; cc < 64; cc++) {
            float4 v4 = *(const float4*)&Vs[cc][tx<<2];
            float vv[4] = {v4.x,v4.y,v4.z,v4.w};
            #pragma unroll
            for (int i = 0; i < 4; i++) {
                float p = KP[(cc<<6) | (((ty<<2)+i) ^ (cc & 28))];
                o[i][0] = fmaf(p, vv[0], o[i][0]);
                o[i][1] = fmaf(p, vv[1], o[i][1]);
                o[i][2] = fmaf(p, vv[2], o[i][2]);
                o[i][3] = fmaf(p, vv[3], o[i][3]);
            }
        }
    }

    const int b = bh >> 4, h = bh & 15;
    #pragma unroll
    for (int i = 0; i < 4; i++) {
        float inv = 1.f / l_i[i];
        int qrow = q0 + (ty<<2) + i;
        float4 v;
        v.x = o[i][0]*inv; v.y = o[i][1]*inv;
        v.z = o[i][2]*inv; v.w = o[i][3]*inv;
        *(float4*)&g_ctx[((size_t)(b*Ss + qrow))*Dd + h*HDIM + (tx<<2)] = v;
    }
}

// ---------------------------------------------------------------------------
// Kernel 4: LayerNorm over D=1024. One block (256 threads) per row.
// ---------------------------------------------------------------------------
__global__ __launch_bounds__(256) void ln_kernel(
    const float* __restrict__ gamma, const float* __restrict__ beta,
    float* __restrict__ out)
{
    const int row = blockIdx.x;
    const int tid = threadIdx.x;
    const float* y = g_y + (size_t)row * Dd;
    float4 v = *(const float4*)&y[tid<<2];
    float s  = v.x + v.y + v.z + v.w;
    float s2 = v.x*v.x + v.y*v.y + v.z*v.z + v.w*v.w;
    #pragma unroll
    for (int ofs = 16; ofs > 0; ofs >>= 1) {
        s  += __shfl_xor_sync(FULLMASK, s,  ofs);
        s2 += __shfl_xor_sync(FULLMASK, s2, ofs);
    }
    __shared__ float ps[8], ps2[8];
    if ((tid & 31) == 0) { ps[tid>>5] = s; ps2[tid>>5] = s2; }
    __syncthreads();
    float tot = 0.f, tot2 = 0.f;
    #pragma unroll
    for (int wdx = 0; wdx < 8; wdx++) { tot += ps[wdx]; tot2 += ps2[wdx]; }
    float mu  = tot * (1.f/1024.f);
    float var = tot2 * (1.f/1024.f) - mu*mu;
    float rstd = rsqrtf(var + 1e-5f);
    float4 g4 = *(const float4*)&gamma[tid<<2];
    float4 b4 = *(const float4*)&beta[tid<<2];
    float4 r;
    r.x = (v.x-mu)*rstd*g4.x + b4.x;
    r.y = (v.y-mu)*rstd*g4.y + b4.y;
    r.z = (v.z-mu)*rstd*g4.z + b4.z;
    r.w = (v.w-mu)*rstd*g4.w + b4.w;
    *(float4*)&out[(size_t)row*Dd + (tid<<2)] = r;
}

// ---------------------------------------------------------------------------
extern "C" void kernel_launch(void* const* d_in, const int* in_sizes, int n_in,
                              void* d_out, int out_size)
{
    const float* x     = (const float*)d_in[0];
    const float* w_in  = (const float*)d_in[1];
    const float* b_in  = (const float*)d_in[2];
    const float* w_out = (const float*)d_in[3];
    const float* b_out = (const float*)d_in[4];
    const float* gamma = (const float*)d_in[5];
    const float* beta  = (const float*)d_in[6];
    float* out = (float*)d_out;

    qkv_gemm_kernel<<<dim3(24, 64), 256>>>(x, w_in, b_in);    // N=3072/128, M=8192/128
    attn_kernel    <<<dim3(32, 64), 256>>>();                 // 32 q-tiles x 64 bh
    out_gemm_kernel<<<dim3(8, 64),  256>>>(x, w_out, b_out);  // N=1024/128
    ln_kernel      <<<8192, 256>>>(gamma, beta, out);
}